// round 3
// baseline (speedup 1.0000x reference)
#include <cuda_runtime.h>
#include <math.h>

#define S_LEN 2048
#define NH    8
#define NB    2
#define DH    64
#define NROWS (NB*NH*S_LEN)   // 32768
#define CAP   256
#define PMQ   132             // Q smem pitch (floats)
#define PMK   130             // K smem pitch (ulonglongs, duplicated values)

// ---- scratch (static device memory; no runtime alloc) ----
__device__ int   g_rowmax[NROWS];
__device__ int   g_rowcnt[NROWS];
__device__ int   g_cidx[(size_t)NROWS * CAP];
__device__ float g_cval[(size_t)NROWS * CAP];

__device__ __forceinline__ unsigned long long dup2(float x){
  unsigned long long r;
  asm("mov.b64 %0, {%1, %1};" : "=l"(r) : "f"(x));
  return r;
}
__device__ __forceinline__ void ffma2(unsigned long long &c, unsigned long long a, unsigned long long b){
  asm("fma.rn.f32x2 %0, %1, %2, %0;" : "+l"(c) : "l"(a), "l"(b));
}
__device__ __forceinline__ float2 unpk(unsigned long long v){
  float2 f;
  asm("mov.b64 {%0, %1}, %2;" : "=f"(f.x), "=f"(f.y) : "l"(v));
  return f;
}

__global__ void init_meta(){
  int i = blockIdx.x * 256 + threadIdx.x;
  if (i < NROWS){ g_rowmax[i] = 0; g_rowcnt[i] = 0; }
}

extern __shared__ float smem1[];

// Kernel 1: fp32 QK^T. Writes zeros to P (final value for ~all entries),
// tracks per-row max + candidate set (qk >= runmax - 0.03).
__global__ __launch_bounds__(256, 2)
void qk_kernel(const float* __restrict__ Q, const float* __restrict__ K,
               const int* __restrict__ mask, float* __restrict__ P)
{
  float* Qs = smem1;                                            // [64][PMQ] transposed
  unsigned long long* Ks2 = (unsigned long long*)(smem1 + 64 * PMQ); // [64][PMK] dup'd
  const int bh = blockIdx.z;
  const int tm = blockIdx.y << 7;
  const int tn = blockIdx.x << 7;
  const float* Qb = Q + ((size_t)bh * S_LEN + tm) * DH;
  const float* Kb = K + ((size_t)bh * S_LEN + tn) * DH;
  const int t = threadIdx.x;
  const int w = t >> 5, lane = t & 31;
  const int wm = w >> 2, wn = w & 3;
  const int lm = lane >> 2, ln = lane & 3;
  const int m0 = (wm << 6) + (lm << 3);
  const int n0 = (wn << 5) + (ln << 3);

  // Zero-store our P region up front (overlaps with everything below).
  {
    const float4 z4 = make_float4(0.f, 0.f, 0.f, 0.f);
    #pragma unroll
    for (int r = 0; r < 8; r++){
      size_t base = ((size_t)bh * S_LEN + tm + m0 + r) * S_LEN + tn + n0;
      *(float4*)(P + base)     = z4;
      *(float4*)(P + base + 4) = z4;
    }
  }

  // Load tiles: Q transposed, K duplicated-packed.
  #pragma unroll
  for (int i = 0; i < 8; i++){
    int idx = (i << 8) + t;
    int row = idx >> 4;
    int kc  = (idx & 15) << 2;
    float4 q = *(const float4*)(Qb + row * DH + kc);
    Qs[(kc+0)*PMQ + row] = q.x; Qs[(kc+1)*PMQ + row] = q.y;
    Qs[(kc+2)*PMQ + row] = q.z; Qs[(kc+3)*PMQ + row] = q.w;
    float4 kk = *(const float4*)(Kb + row * DH + kc);
    Ks2[(kc+0)*PMK + row] = dup2(kk.x); Ks2[(kc+1)*PMK + row] = dup2(kk.y);
    Ks2[(kc+2)*PMK + row] = dup2(kk.z); Ks2[(kc+3)*PMK + row] = dup2(kk.w);
  }
  __syncthreads();

  unsigned long long acc[4][8];
  #pragma unroll
  for (int i = 0; i < 4; i++)
    #pragma unroll
    for (int j = 0; j < 8; j++) acc[i][j] = 0ULL;

  #pragma unroll 8
  for (int k = 0; k < 64; k++){
    const float* qp = &Qs[k * PMQ + m0];
    const unsigned long long* kp = &Ks2[k * PMK + n0];
    ulonglong2 a01 = *(const ulonglong2*)(qp);
    ulonglong2 a23 = *(const ulonglong2*)(qp + 4);
    ulonglong2 b01 = *(const ulonglong2*)(kp);
    ulonglong2 b23 = *(const ulonglong2*)(kp + 2);
    ulonglong2 b45 = *(const ulonglong2*)(kp + 4);
    ulonglong2 b67 = *(const ulonglong2*)(kp + 6);
    unsigned long long ap[4] = {a01.x, a01.y, a23.x, a23.y};
    unsigned long long bd[8] = {b01.x, b01.y, b23.x, b23.y, b45.x, b45.y, b67.x, b67.y};
    #pragma unroll
    for (int r = 0; r < 4; r++)
      #pragma unroll
      for (int c = 0; c < 8; c++)
        ffma2(acc[r][c], ap[r], bd[c]);
  }

  // Epilogue: per-row masked max -> global atomicMax -> candidate append.
  const int b = bh >> 3;
  int mk[8];
  #pragma unroll
  for (int j = 0; j < 8; j++) mk[j] = mask[b * S_LEN + tn + n0 + j];

  #pragma unroll
  for (int r = 0; r < 4; r++){
    float2 f[8];
    #pragma unroll
    for (int c = 0; c < 8; c++) f[c] = unpk(acc[r][c]);
    #pragma unroll
    for (int half = 0; half < 2; half++){
      float v[8];
      #pragma unroll
      for (int c = 0; c < 8; c++) v[c] = half ? f[c].y : f[c].x;
      float lmax = -1e9f;
      #pragma unroll
      for (int c = 0; c < 8; c++) if (mk[c]) lmax = fmaxf(lmax, v[c]);
      // reduce over the 4 ln lanes sharing this row
      float m1 = fmaxf(lmax, __shfl_xor_sync(0xffffffffu, lmax, 1));
      float m2 = fmaxf(m1,   __shfl_xor_sync(0xffffffffu, m1,   2));
      const int grow = bh * S_LEN + tm + m0 + 2*r + half;
      float newmax = 0.0f;
      if ((lane & 3) == 0){
        int old = atomicMax(&g_rowmax[grow], __float_as_int(m2));
        newmax = fmaxf(m2, __int_as_float(old));
      }
      newmax = __shfl_sync(0xffffffffu, newmax, lane & ~3);
      const float th = newmax - 0.03f;
      #pragma unroll
      for (int c = 0; c < 8; c++){
        if (mk[c] && v[c] >= th){
          int pos = atomicAdd(&g_rowcnt[grow], 1);
          if (pos < CAP){
            g_cidx[(size_t)grow * CAP + pos] = tn + n0 + c;
            g_cval[(size_t)grow * CAP + pos] = v[c];
          }
        }
      }
    }
  }
}

// Kernel 2: per-row candidate softmax scatter + out. Exact fallback for
// pathological rows (cap overflow / low max / fully masked).
__global__ __launch_bounds__(128)
void scatter_pv(const float* __restrict__ Q, const float* __restrict__ K,
                const float* __restrict__ V, const int* __restrict__ mask,
                float* __restrict__ P, float* __restrict__ Out)
{
  __shared__ float sval[CAP];
  __shared__ int   sidx[CAP];
  __shared__ float nzp[CAP];
  __shared__ int   nzidx[CAP];
  __shared__ float red[4];
  __shared__ int   snnz;
  __shared__ float sh_scalar;

  const int row = blockIdx.x;
  const int bh  = row >> 11;
  const int t = threadIdx.x;
  const int w = t >> 5, lane = t & 31;
  const float* Vb = V + (size_t)bh * S_LEN * DH;
  float* Pr = P + (size_t)row * S_LEN;

  const int   cnt   = g_rowcnt[row];
  const float qkmax = __int_as_float(g_rowmax[row]);

  if (cnt > 0 && cnt <= CAP && qkmax >= 14.0f){
    for (int i = t; i < cnt; i += 128){
      sidx[i] = g_cidx[(size_t)row * CAP + i];
      sval[i] = g_cval[(size_t)row * CAP + i];
    }
    if (t == 0) snnz = 0;
    __syncthreads();
    const float smaxv = expf(qkmax) * 0.125f;
    float ls = 0.0f;
    for (int i = t; i < cnt; i += 128){
      float e = expf(expf(sval[i]) * 0.125f - smaxv);
      sval[i] = e;
      ls += e;
    }
    #pragma unroll
    for (int off = 16; off; off >>= 1) ls += __shfl_xor_sync(0xffffffffu, ls, off);
    if (lane == 0) red[w] = ls;
    __syncthreads();
    const float inv = 1.0f / (red[0] + red[1] + red[2] + red[3]);
    for (int i = t; i < cnt; i += 128){
      float p = sval[i] * inv;
      Pr[sidx[i]] = p;
      if (p != 0.0f){
        int pos = atomicAdd(&snnz, 1);
        nzp[pos] = p; nzidx[pos] = sidx[i];
      }
    }
    __syncthreads();
    if (t < DH){
      float acc = 0.0f;
      int nz = snnz;
      for (int c = 0; c < nz; c++)
        acc += nzp[c] * Vb[(size_t)nzidx[c] * DH + t];
      Out[(size_t)row * DH + t] = acc;
    }
  } else {
    // ---- exact fallback: full-row recompute (matches reference semantics) ----
    __shared__ float qrow[DH];
    __shared__ float qk[S_LEN];
    const float* Qr = Q + (size_t)row * DH;
    if (t < DH) qrow[t] = Qr[t];
    __syncthreads();
    const int b = bh >> 3;
    const float* Kb = K + (size_t)bh * S_LEN * DH;
    for (int key = t; key < S_LEN; key += 128){
      float acc = 0.0f;
      #pragma unroll 16
      for (int d = 0; d < DH; d++) acc += qrow[d] * Kb[(size_t)key * DH + d];
      qk[key] = mask[b * S_LEN + key] ? acc : -1e9f;
    }
    __syncthreads();
    float mx = -3.0e38f;
    for (int key = t; key < S_LEN; key += 128) mx = fmaxf(mx, qk[key]);
    #pragma unroll
    for (int off = 16; off; off >>= 1) mx = fmaxf(mx, __shfl_xor_sync(0xffffffffu, mx, off));
    if (lane == 0) red[w] = mx;
    __syncthreads();
    if (t == 0) sh_scalar = fmaxf(fmaxf(red[0], red[1]), fmaxf(red[2], red[3]));
    __syncthreads();
    const float qmax = sh_scalar;
    const float smax_s = (qmax <= -1e8f) ? -1e9f : expf(qmax) * 0.125f;
    float ls = 0.0f;
    for (int key = t; key < S_LEN; key += 128){
      float s = (qk[key] <= -1e8f) ? -1e9f : expf(qk[key]) * 0.125f;
      float e = expf(s - smax_s);
      qk[key] = e;
      ls += e;
    }
    #pragma unroll
    for (int off = 16; off; off >>= 1) ls += __shfl_xor_sync(0xffffffffu, ls, off);
    if (lane == 0) red[w] = ls;
    __syncthreads();
    if (t == 0) sh_scalar = red[0] + red[1] + red[2] + red[3];
    __syncthreads();
    const float inv = 1.0f / sh_scalar;
    for (int key = t; key < S_LEN; key += 128) Pr[key] = qk[key] * inv;
    __syncthreads();
    if (t < DH){
      float acc = 0.0f;
      for (int key = 0; key < S_LEN; key++)
        acc += qk[key] * inv * Vb[(size_t)key * DH + t];
      Out[(size_t)row * DH + t] = acc;
    }
  }
}

extern "C" void kernel_launch(void* const* d_in, const int* in_sizes, int n_in,
                              void* d_out, int out_size)
{
  const float* Q    = (const float*)d_in[0];
  const float* K    = (const float*)d_in[1];
  const float* V    = (const float*)d_in[2];
  const int*   mask = (const int*)d_in[3];

  float* Out = (float*)d_out;                        // (B,H,S,D)
  float* P   = Out + (size_t)NB * NH * S_LEN * DH;   // (B,H,S,S)

  init_meta<<<NROWS / 256, 256>>>();

  const int smem = 64 * PMQ * sizeof(float) + 64 * PMK * sizeof(unsigned long long); // 100352
  cudaFuncSetAttribute(qk_kernel, cudaFuncAttributeMaxDynamicSharedMemorySize, smem);
  dim3 g1(S_LEN / 128, S_LEN / 128, NB * NH);
  qk_kernel<<<g1, 256, smem>>>(Q, K, mask, P);

  scatter_pv<<<NROWS, 128>>>(Q, K, V, mask, P, Out);
}

// round 5
// speedup vs baseline: 1.2114x; 1.2114x over previous
#include <cuda_runtime.h>
#include <math.h>

#define S_LEN 2048
#define NH    8
#define NB    2
#define DH    64
#define NROWS (NB*NH*S_LEN)   // 32768
#define CAP   256
#define PM    132             // smem pitch (floats)

// ---- scratch (static device memory; zero-initialized at load) ----
__device__ int   g_rowmax[NROWS];
__device__ int   g_rowcnt[NROWS];
__device__ int   g_cidx[(size_t)NROWS * CAP];
__device__ float g_cval[(size_t)NROWS * CAP];

__device__ __forceinline__ unsigned long long dup2(float x){
  unsigned long long r;
  asm("mov.b64 %0, {%1, %1};" : "=l"(r) : "f"(x));
  return r;
}
__device__ __forceinline__ void ffma2(unsigned long long &c, unsigned long long a, unsigned long long b){
  asm("fma.rn.f32x2 %0, %1, %2, %0;" : "+l"(c) : "l"(a), "l"(b));
}
__device__ __forceinline__ float2 unpk(unsigned long long v){
  float2 f;
  asm("mov.b64 {%0, %1}, %2;" : "=f"(f.x), "=f"(f.y) : "l"(v));
  return f;
}

extern __shared__ float smem1[];

// Kernel 1: fp32 QK^T (R2 inner loop, conflict-free smem). Writes ZEROS to P
// (final value for ~all entries), tracks per-row max + candidates.
__global__ __launch_bounds__(256, 2)
void qk_kernel(const float* __restrict__ Q, const float* __restrict__ K,
               const int* __restrict__ mask, float* __restrict__ P)
{
  float* Qs = smem1;              // [64][PM], transposed: Qs[k][m]
  float* Ks = smem1 + 64 * PM;    // [64][PM]
  const int bh = blockIdx.z;
  const int tm = blockIdx.y << 7;
  const int tn = blockIdx.x << 7;
  const float* Qb = Q + ((size_t)bh * S_LEN + tm) * DH;
  const float* Kb = K + ((size_t)bh * S_LEN + tn) * DH;
  const int t = threadIdx.x;
  const int w = t >> 5, lane = t & 31;
  const int wm = w >> 2, wn = w & 3;
  const int lm = lane >> 2, ln = lane & 3;
  const int m0 = (wm << 6) + (lm << 3);
  const int n0 = (wn << 5) + (ln << 3);

  // Zero-store our 8x16-per-thread P region up front (overlaps with compute).
  {
    const float4 z4 = make_float4(0.f, 0.f, 0.f, 0.f);
    #pragma unroll
    for (int r = 0; r < 8; r++){
      size_t base = ((size_t)bh * S_LEN + tm + m0 + r) * S_LEN + tn + n0;
      *(float4*)(P + base)     = z4;
      *(float4*)(P + base + 4) = z4;
    }
  }

  // Load 128x64 tiles, transposing into smem (conflict-free).
  #pragma unroll
  for (int i = 0; i < 8; i++){
    int idx = (i << 8) + t;
    int row = idx >> 4;
    int kc  = (idx & 15) << 2;
    float4 q = *(const float4*)(Qb + row * DH + kc);
    Qs[(kc+0)*PM + row] = q.x; Qs[(kc+1)*PM + row] = q.y;
    Qs[(kc+2)*PM + row] = q.z; Qs[(kc+3)*PM + row] = q.w;
    float4 kk = *(const float4*)(Kb + row * DH + kc);
    Ks[(kc+0)*PM + row] = kk.x; Ks[(kc+1)*PM + row] = kk.y;
    Ks[(kc+2)*PM + row] = kk.z; Ks[(kc+3)*PM + row] = kk.w;
  }
  __syncthreads();

  unsigned long long acc[4][8];
  #pragma unroll
  for (int i = 0; i < 4; i++)
    #pragma unroll
    for (int j = 0; j < 8; j++) acc[i][j] = 0ULL;

  #pragma unroll 16
  for (int k = 0; k < 64; k++){
    const float* qp = &Qs[k * PM + m0];
    const float* kp = &Ks[k * PM + n0];
    ulonglong2 a01 = *(const ulonglong2*)(qp);
    ulonglong2 a23 = *(const ulonglong2*)(qp + 4);
    float4 b0 = *(const float4*)(kp);
    float4 b1 = *(const float4*)(kp + 4);
    unsigned long long ap[4] = {a01.x, a01.y, a23.x, a23.y};
    unsigned long long bd[8] = {dup2(b0.x), dup2(b0.y), dup2(b0.z), dup2(b0.w),
                                dup2(b1.x), dup2(b1.y), dup2(b1.z), dup2(b1.w)};
    #pragma unroll
    for (int r = 0; r < 4; r++)
      #pragma unroll
      for (int c = 0; c < 8; c++)
        ffma2(acc[r][c], ap[r], bd[c]);
  }

  // Epilogue: per-row masked max -> global atomicMax -> candidate append.
  const int b = bh >> 3;
  int mk[8];
  #pragma unroll
  for (int j = 0; j < 8; j++) mk[j] = mask[b * S_LEN + tn + n0 + j];

  #pragma unroll
  for (int r = 0; r < 4; r++){
    float2 f[8];
    #pragma unroll
    for (int c = 0; c < 8; c++) f[c] = unpk(acc[r][c]);
    #pragma unroll
    for (int half = 0; half < 2; half++){
      float v[8];
      #pragma unroll
      for (int c = 0; c < 8; c++) v[c] = half ? f[c].y : f[c].x;
      float lmax = -1e9f;
      #pragma unroll
      for (int c = 0; c < 8; c++) if (mk[c]) lmax = fmaxf(lmax, v[c]);
      // reduce over the 4 ln lanes sharing this row
      float m1 = fmaxf(lmax, __shfl_xor_sync(0xffffffffu, lmax, 1));
      float m2 = fmaxf(m1,   __shfl_xor_sync(0xffffffffu, m1,   2));
      const int grow = bh * S_LEN + tm + m0 + 2*r + half;
      float newmax = 0.0f;
      if ((lane & 3) == 0){
        int old = atomicMax(&g_rowmax[grow], __float_as_int(m2));
        newmax = fmaxf(m2, __int_as_float(old));
      }
      newmax = __shfl_sync(0xffffffffu, newmax, lane & ~3);
      const float th = newmax - 0.03f;
      #pragma unroll
      for (int c = 0; c < 8; c++){
        if (mk[c] && v[c] >= th){
          int pos = atomicAdd(&g_rowcnt[grow], 1);
          if (pos < CAP){
            g_cidx[(size_t)grow * CAP + pos] = tn + n0 + c;
            g_cval[(size_t)grow * CAP + pos] = v[c];
          }
        }
      }
    }
  }
}

// Kernel 2: per-row candidate softmax scatter + out; resets metadata for the
// next graph replay (AFTER a barrier — all threads read first).
__global__ __launch_bounds__(128)
void scatter_pv(const float* __restrict__ Q, const float* __restrict__ K,
                const float* __restrict__ V, const int* __restrict__ mask,
                float* __restrict__ P, float* __restrict__ Out)
{
  __shared__ float sval[CAP];
  __shared__ int   sidx[CAP];
  __shared__ float nzp[CAP];
  __shared__ int   nzidx[CAP];
  __shared__ float red[4];
  __shared__ int   snnz;
  __shared__ float sh_scalar;

  const int row = blockIdx.x;
  const int bh  = row >> 11;
  const int t = threadIdx.x;
  const int w = t >> 5, lane = t & 31;
  const float* Vb = V + (size_t)bh * S_LEN * DH;
  float* Pr = P + (size_t)row * S_LEN;

  const int   cnt   = g_rowcnt[row];
  const float qkmax = __int_as_float(g_rowmax[row]);
  __syncthreads();   // every thread has read cnt/qkmax before the reset below
  if (t == 0){ g_rowcnt[row] = 0; g_rowmax[row] = 0; }

  if (cnt > 0 && cnt <= CAP && qkmax >= 14.0f){
    for (int i = t; i < cnt; i += 128){
      sidx[i] = g_cidx[(size_t)row * CAP + i];
      sval[i] = g_cval[(size_t)row * CAP + i];
    }
    if (t == 0) snnz = 0;
    __syncthreads();
    const float smaxv = expf(qkmax) * 0.125f;
    float ls = 0.0f;
    for (int i = t; i < cnt; i += 128){
      float e = expf(expf(sval[i]) * 0.125f - smaxv);
      sval[i] = e;
      ls += e;
    }
    #pragma unroll
    for (int off = 16; off; off >>= 1) ls += __shfl_xor_sync(0xffffffffu, ls, off);
    if (lane == 0) red[w] = ls;
    __syncthreads();
    const float inv = 1.0f / (red[0] + red[1] + red[2] + red[3]);
    for (int i = t; i < cnt; i += 128){
      float p = sval[i] * inv;
      Pr[sidx[i]] = p;
      if (p != 0.0f){
        int pos = atomicAdd(&snnz, 1);
        nzp[pos] = p; nzidx[pos] = sidx[i];
      }
    }
    __syncthreads();
    if (t < DH){
      float acc = 0.0f;
      int nz = snnz;
      for (int c = 0; c < nz; c++)
        acc += nzp[c] * Vb[(size_t)nzidx[c] * DH + t];
      Out[(size_t)row * DH + t] = acc;
    }
  } else {
    // ---- exact fallback: full-row recompute (reference semantics) ----
    __shared__ float qrow[DH];
    __shared__ float qk[S_LEN];
    const float* Qr = Q + (size_t)row * DH;
    if (t < DH) qrow[t] = Qr[t];
    __syncthreads();
    const int b = bh >> 3;
    const float* Kb = K + (size_t)bh * S_LEN * DH;
    for (int key = t; key < S_LEN; key += 128){
      float acc = 0.0f;
      #pragma unroll 16
      for (int d = 0; d < DH; d++) acc += qrow[d] * Kb[(size_t)key * DH + d];
      qk[key] = mask[b * S_LEN + key] ? acc : -1e9f;
    }
    __syncthreads();
    float mx = -3.0e38f;
    for (int key = t; key < S_LEN; key += 128) mx = fmaxf(mx, qk[key]);
    #pragma unroll
    for (int off = 16; off; off >>= 1) mx = fmaxf(mx, __shfl_xor_sync(0xffffffffu, mx, off));
    if (lane == 0) red[w] = mx;
    __syncthreads();
    if (t == 0) sh_scalar = fmaxf(fmaxf(red[0], red[1]), fmaxf(red[2], red[3]));
    __syncthreads();
    const float qmax = sh_scalar;
    const float smax_s = (qmax <= -1e8f) ? -1e9f : expf(qmax) * 0.125f;
    float ls = 0.0f;
    for (int key = t; key < S_LEN; key += 128){
      float s = (qk[key] <= -1e8f) ? -1e9f : expf(qk[key]) * 0.125f;
      float e = expf(s - smax_s);
      qk[key] = e;
      ls += e;
    }
    #pragma unroll
    for (int off = 16; off; off >>= 1) ls += __shfl_xor_sync(0xffffffffu, ls, off);
    if (lane == 0) red[w] = ls;
    __syncthreads();
    if (t == 0) sh_scalar = red[0] + red[1] + red[2] + red[3];
    __syncthreads();
    const float inv = 1.0f / sh_scalar;
    for (int key = t; key < S_LEN; key += 128) Pr[key] = qk[key] * inv;
    __syncthreads();
    if (t < DH){
      float acc = 0.0f;
      for (int key = 0; key < S_LEN; key++)
        acc += qk[key] * inv * Vb[(size_t)key * DH + t];
      Out[(size_t)row * DH + t] = acc;
    }
  }
}

extern "C" void kernel_launch(void* const* d_in, const int* in_sizes, int n_in,
                              void* d_out, int out_size)
{
  const float* Q    = (const float*)d_in[0];
  const float* K    = (const float*)d_in[1];
  const float* V    = (const float*)d_in[2];
  const int*   mask = (const int*)d_in[3];

  float* Out = (float*)d_out;                        // (B,H,S,D)
  float* P   = Out + (size_t)NB * NH * S_LEN * DH;   // (B,H,S,S)

  const int smem = 2 * 64 * PM * sizeof(float);      // 67.6 KB -> 2 CTAs/SM
  cudaFuncSetAttribute(qk_kernel, cudaFuncAttributeMaxDynamicSharedMemorySize, smem);
  dim3 g1(S_LEN / 128, S_LEN / 128, NB * NH);
  qk_kernel<<<g1, 256, smem>>>(Q, K, mask, P);

  scatter_pv<<<NROWS, 128>>>(Q, K, V, mask, P, Out);
}

// round 6
// speedup vs baseline: 1.5117x; 1.2479x over previous
#include <cuda_runtime.h>
#include <math.h>

#define S_LEN 2048
#define NH    8
#define NB    2
#define DH    64
#define NROWS (NB*NH*S_LEN)   // 32768
#define CAP   256
#define PM    132             // smem pitch (floats)

// ---- scratch (static device memory; zero-initialized at load) ----
__device__ int   g_rowmax[NROWS];
__device__ int   g_rowcnt[NROWS];
__device__ int   g_cidx[(size_t)NROWS * CAP];
__device__ float g_cval[(size_t)NROWS * CAP];

__device__ __forceinline__ unsigned long long dup2(float x){
  unsigned long long r;
  asm("mov.b64 %0, {%1, %1};" : "=l"(r) : "f"(x));
  return r;
}
__device__ __forceinline__ void ffma2(unsigned long long &c, unsigned long long a, unsigned long long b){
  asm("fma.rn.f32x2 %0, %1, %2, %0;" : "+l"(c) : "l"(a), "l"(b));
}
__device__ __forceinline__ float2 unpk(unsigned long long v){
  float2 f;
  asm("mov.b64 {%0, %1}, %2;" : "=f"(f.x), "=f"(f.y) : "l"(v));
  return f;
}

extern __shared__ float smem1[];

// Kernel 1: fp32 QK^T (R2 inner loop, conflict-free smem). Writes ZEROS to P
// (final value for ~all entries), tracks per-row max + candidates.
// (Byte-identical to the R5 passing version.)
__global__ __launch_bounds__(256, 2)
void qk_kernel(const float* __restrict__ Q, const float* __restrict__ K,
               const int* __restrict__ mask, float* __restrict__ P)
{
  float* Qs = smem1;              // [64][PM], transposed: Qs[k][m]
  float* Ks = smem1 + 64 * PM;    // [64][PM]
  const int bh = blockIdx.z;
  const int tm = blockIdx.y << 7;
  const int tn = blockIdx.x << 7;
  const float* Qb = Q + ((size_t)bh * S_LEN + tm) * DH;
  const float* Kb = K + ((size_t)bh * S_LEN + tn) * DH;
  const int t = threadIdx.x;
  const int w = t >> 5, lane = t & 31;
  const int wm = w >> 2, wn = w & 3;
  const int lm = lane >> 2, ln = lane & 3;
  const int m0 = (wm << 6) + (lm << 3);
  const int n0 = (wn << 5) + (ln << 3);

  // Zero-store our 8x16-per-thread P region up front (overlaps with compute).
  {
    const float4 z4 = make_float4(0.f, 0.f, 0.f, 0.f);
    #pragma unroll
    for (int r = 0; r < 8; r++){
      size_t base = ((size_t)bh * S_LEN + tm + m0 + r) * S_LEN + tn + n0;
      *(float4*)(P + base)     = z4;
      *(float4*)(P + base + 4) = z4;
    }
  }

  // Load 128x64 tiles, transposing into smem (conflict-free).
  #pragma unroll
  for (int i = 0; i < 8; i++){
    int idx = (i << 8) + t;
    int row = idx >> 4;
    int kc  = (idx & 15) << 2;
    float4 q = *(const float4*)(Qb + row * DH + kc);
    Qs[(kc+0)*PM + row] = q.x; Qs[(kc+1)*PM + row] = q.y;
    Qs[(kc+2)*PM + row] = q.z; Qs[(kc+3)*PM + row] = q.w;
    float4 kk = *(const float4*)(Kb + row * DH + kc);
    Ks[(kc+0)*PM + row] = kk.x; Ks[(kc+1)*PM + row] = kk.y;
    Ks[(kc+2)*PM + row] = kk.z; Ks[(kc+3)*PM + row] = kk.w;
  }
  __syncthreads();

  unsigned long long acc[4][8];
  #pragma unroll
  for (int i = 0; i < 4; i++)
    #pragma unroll
    for (int j = 0; j < 8; j++) acc[i][j] = 0ULL;

  #pragma unroll 16
  for (int k = 0; k < 64; k++){
    const float* qp = &Qs[k * PM + m0];
    const float* kp = &Ks[k * PM + n0];
    ulonglong2 a01 = *(const ulonglong2*)(qp);
    ulonglong2 a23 = *(const ulonglong2*)(qp + 4);
    float4 b0 = *(const float4*)(kp);
    float4 b1 = *(const float4*)(kp + 4);
    unsigned long long ap[4] = {a01.x, a01.y, a23.x, a23.y};
    unsigned long long bd[8] = {dup2(b0.x), dup2(b0.y), dup2(b0.z), dup2(b0.w),
                                dup2(b1.x), dup2(b1.y), dup2(b1.z), dup2(b1.w)};
    #pragma unroll
    for (int r = 0; r < 4; r++)
      #pragma unroll
      for (int c = 0; c < 8; c++)
        ffma2(acc[r][c], ap[r], bd[c]);
  }

  // Epilogue: per-row masked max -> global atomicMax -> candidate append.
  const int b = bh >> 3;
  int mk[8];
  #pragma unroll
  for (int j = 0; j < 8; j++) mk[j] = mask[b * S_LEN + tn + n0 + j];

  #pragma unroll
  for (int r = 0; r < 4; r++){
    float2 f[8];
    #pragma unroll
    for (int c = 0; c < 8; c++) f[c] = unpk(acc[r][c]);
    #pragma unroll
    for (int half = 0; half < 2; half++){
      float v[8];
      #pragma unroll
      for (int c = 0; c < 8; c++) v[c] = half ? f[c].y : f[c].x;
      float lmax = -1e9f;
      #pragma unroll
      for (int c = 0; c < 8; c++) if (mk[c]) lmax = fmaxf(lmax, v[c]);
      float m1 = fmaxf(lmax, __shfl_xor_sync(0xffffffffu, lmax, 1));
      float m2 = fmaxf(m1,   __shfl_xor_sync(0xffffffffu, m1,   2));
      const int grow = bh * S_LEN + tm + m0 + 2*r + half;
      float newmax = 0.0f;
      if ((lane & 3) == 0){
        int old = atomicMax(&g_rowmax[grow], __float_as_int(m2));
        newmax = fmaxf(m2, __int_as_float(old));
      }
      newmax = __shfl_sync(0xffffffffu, newmax, lane & ~3);
      const float th = newmax - 0.03f;
      #pragma unroll
      for (int c = 0; c < 8; c++){
        if (mk[c] && v[c] >= th){
          int pos = atomicAdd(&g_rowcnt[grow], 1);
          if (pos < CAP){
            g_cidx[(size_t)grow * CAP + pos] = tn + n0 + c;
            g_cval[(size_t)grow * CAP + pos] = v[c];
          }
        }
      }
    }
  }
}

// Kernel 2: warp-per-row candidate softmax scatter + out. No __syncthreads.
__global__ __launch_bounds__(256)
void scatter_pv(const float* __restrict__ Q, const float* __restrict__ K,
                const float* __restrict__ V, const int* __restrict__ mask,
                float* __restrict__ P, float* __restrict__ Out)
{
  const int wid  = threadIdx.x >> 5;
  const int lane = threadIdx.x & 31;
  const int row  = (blockIdx.x << 3) + wid;
  const int bh   = row >> 11;
  const float* Vb = V + (size_t)bh * S_LEN * DH;
  float* Pr = P + (size_t)row * S_LEN;

  // Speculative first-chunk candidate loads (always-valid static memory).
  const size_t cbase = (size_t)row * CAP;
  int   spec_idx = g_cidx[cbase + lane];
  float spec_val = g_cval[cbase + lane];

  const int   cnt   = g_rowcnt[row];
  const float qkmax = __int_as_float(g_rowmax[row]);
  // Reset for next graph replay. Single warp owns this row; the loads above
  // were issued by this same warp instruction stream, so no race.
  if (lane == 0){ g_rowcnt[row] = 0; g_rowmax[row] = 0; }

  if (cnt > 0 && cnt <= CAP && qkmax >= 14.0f){
    const float smaxv = expf(qkmax) * 0.125f;
    const int nchunk = (cnt + 31) >> 5;
    float evals[CAP/32];
    int   idxs [CAP/32];
    float lsum = 0.0f;
    {
      float e = 0.0f;
      if (lane < cnt){ e = expf(expf(spec_val) * 0.125f - smaxv); lsum += e; }
      evals[0] = e; idxs[0] = spec_idx;
    }
    for (int c = 1; c < nchunk; c++){
      int i = (c << 5) + lane;
      float e = 0.0f; int id = 0;
      if (i < cnt){
        id = g_cidx[cbase + i];
        e  = expf(expf(g_cval[cbase + i]) * 0.125f - smaxv);
        lsum += e;
      }
      evals[c] = e; idxs[c] = id;
    }
    #pragma unroll
    for (int off = 16; off; off >>= 1) lsum += __shfl_xor_sync(0xffffffffu, lsum, off);
    const float inv = 1.0f / lsum;

    float o0 = 0.0f, o1 = 0.0f;
    for (int c = 0; c < nchunk; c++){
      int i = (c << 5) + lane;
      float p = evals[c] * inv;
      if (i < cnt) Pr[idxs[c]] = p;
      unsigned mnz = __ballot_sync(0xffffffffu, (i < cnt) && (p != 0.0f));
      while (mnz){
        int src = __ffs(mnz) - 1; mnz &= mnz - 1;
        float pv = __shfl_sync(0xffffffffu, p, src);
        int  key = __shfl_sync(0xffffffffu, idxs[c], src);
        const float* vr = Vb + (size_t)key * DH;
        o0 += pv * vr[lane];
        o1 += pv * vr[lane + 32];
      }
    }
    Out[(size_t)row * DH + lane]      = o0;
    Out[(size_t)row * DH + lane + 32] = o1;
  } else {
    // ---- exact fallback (reference semantics), warp-only, 3-pass ----
    const float* Qr = Q + (size_t)row * DH;
    const float* Kb = K + (size_t)bh * S_LEN * DH;
    const int*   mrow = mask + (bh >> 3) * S_LEN;

    // pass 1: row max
    float mx = -3.0e38f;
    for (int key = lane; key < S_LEN; key += 32){
      float acc = 0.0f;
      #pragma unroll 16
      for (int d = 0; d < DH; d++) acc += Qr[d] * Kb[(size_t)key * DH + d];
      float qkv = mrow[key] ? acc : -1e9f;
      mx = fmaxf(mx, qkv);
    }
    #pragma unroll
    for (int off = 16; off; off >>= 1) mx = fmaxf(mx, __shfl_xor_sync(0xffffffffu, mx, off));
    const float qmax = mx;
    const float smax_s = (qmax <= -1e8f) ? -1e9f : expf(qmax) * 0.125f;

    // pass 2: sum of e
    float lsum = 0.0f;
    for (int key = lane; key < S_LEN; key += 32){
      float acc = 0.0f;
      #pragma unroll 16
      for (int d = 0; d < DH; d++) acc += Qr[d] * Kb[(size_t)key * DH + d];
      float qkv = mrow[key] ? acc : -1e9f;
      float s = (qkv <= -1e8f) ? -1e9f : expf(qkv) * 0.125f;
      lsum += expf(s - smax_s);
    }
    #pragma unroll
    for (int off = 16; off; off >>= 1) lsum += __shfl_xor_sync(0xffffffffu, lsum, off);
    const float inv = 1.0f / lsum;

    // pass 3: write P, accumulate out
    float o0 = 0.0f, o1 = 0.0f;
    for (int key0 = 0; key0 < S_LEN; key0 += 32){
      int key = key0 + lane;
      float acc = 0.0f;
      #pragma unroll 16
      for (int d = 0; d < DH; d++) acc += Qr[d] * Kb[(size_t)key * DH + d];
      float qkv = mrow[key] ? acc : -1e9f;
      float s = (qkv <= -1e8f) ? -1e9f : expf(qkv) * 0.125f;
      float p = expf(s - smax_s) * inv;
      Pr[key] = p;
      #pragma unroll
      for (int src = 0; src < 32; src++){
        float pv = __shfl_sync(0xffffffffu, p, src);
        if (pv != 0.0f){
          const float* vr = Vb + (size_t)(key0 + src) * DH;
          o0 += pv * vr[lane];
          o1 += pv * vr[lane + 32];
        }
      }
    }
    Out[(size_t)row * DH + lane]      = o0;
    Out[(size_t)row * DH + lane + 32] = o1;
  }
}

extern "C" void kernel_launch(void* const* d_in, const int* in_sizes, int n_in,
                              void* d_out, int out_size)
{
  const float* Q    = (const float*)d_in[0];
  const float* K    = (const float*)d_in[1];
  const float* V    = (const float*)d_in[2];
  const int*   mask = (const int*)d_in[3];

  float* Out = (float*)d_out;                        // (B,H,S,D)
  float* P   = Out + (size_t)NB * NH * S_LEN * DH;   // (B,H,S,S)

  const int smem = 2 * 64 * PM * sizeof(float);      // 67.6 KB -> 2 CTAs/SM
  cudaFuncSetAttribute(qk_kernel, cudaFuncAttributeMaxDynamicSharedMemorySize, smem);
  dim3 g1(S_LEN / 128, S_LEN / 128, NB * NH);
  qk_kernel<<<g1, 256, smem>>>(Q, K, mask, P);

  scatter_pv<<<NROWS / 8, 256>>>(Q, K, V, mask, P, Out);
}

// round 8
// speedup vs baseline: 1.5195x; 1.0052x over previous
#include <cuda_runtime.h>
#include <stdint.h>
#include <math.h>

#define S_LEN 2048
#define NH    8
#define NB    2
#define DH    64
#define NROWS (NB*NH*S_LEN)   // 32768
#define CAP   256
#define PT    68              // smem tile pitch (elements)

// ---- scratch (static device memory; zero-initialized at load) ----
__device__ int   g_rowmax[NROWS];
__device__ int   g_rowcnt[NROWS];
__device__ int   g_cidx[(size_t)NROWS * CAP];
__device__ float g_cval[(size_t)NROWS * CAP];

__device__ __forceinline__ uint32_t cvt_tf32(float x){
  uint32_t r;
  asm("cvt.rna.tf32.f32 %0, %1;" : "=r"(r) : "f"(x));
  return r;
}
__device__ __forceinline__ void mma_tf32(float* c, const uint32_t* a, uint32_t b0, uint32_t b1){
  asm volatile(
    "mma.sync.aligned.m16n8k8.row.col.f32.tf32.tf32.f32 "
    "{%0,%1,%2,%3}, {%4,%5,%6,%7}, {%8,%9}, {%0,%1,%2,%3};"
    : "+f"(c[0]), "+f"(c[1]), "+f"(c[2]), "+f"(c[3])
    : "r"(a[0]), "r"(a[1]), "r"(a[2]), "r"(a[3]), "r"(b0), "r"(b1));
}

// ===================== Kernel 1: tf32 mma.sync QK^T =====================
// Per CTA: 128x128 tile. Zeros P, finds per-row candidates
// (approx qk >= rowmax - 0.19), recomputes them exactly in fp32.
__global__ __launch_bounds__(256, 2)
void qk_mma(const float* __restrict__ Q, const float* __restrict__ K,
            const int* __restrict__ mask, float* __restrict__ P)
{
  extern __shared__ char sm[];
  int* smask = (int*)sm;                                  // [128]
  uint32_t* Qs = (uint32_t*)(sm + 512);                   // [128][PT] tf32 bits
  uint32_t* Ks = (uint32_t*)(sm + 512 + 128 * PT * 4);    // [128][PT]

  const int bh = blockIdx.z;
  const int tm = blockIdx.y << 7;
  const int tn = blockIdx.x << 7;
  const int t = threadIdx.x;
  const int wid = t >> 5, lane = t & 31;
  const int wm = wid >> 1, wn = wid & 1;   // warps: 4 over M, 2 over N
  const int g  = lane >> 2, qd = lane & 3;
  const int b  = bh >> 3;
  const float* Qb = Q + ((size_t)bh * S_LEN + tm) * DH;
  const float* Kb = K + ((size_t)bh * S_LEN + tn) * DH;

  if (t < 128) smask[t] = mask[b * S_LEN + tn + t];

  // Zero-store this CTA's P tile (final value for non-candidates).
  {
    const float4 z4 = make_float4(0.f, 0.f, 0.f, 0.f);
    int row = t & 127, half = t >> 7;
    float* Pr = P + ((size_t)bh * S_LEN + tm + row) * S_LEN + tn + (half << 6);
    #pragma unroll
    for (int c = 0; c < 16; c++) *(float4*)(Pr + (c << 2)) = z4;
  }

  // Load tiles, convert to tf32 (rna) into smem.
  #pragma unroll
  for (int i = 0; i < 8; i++){
    int idx = (i << 8) + t;            // 0..2047
    int row = idx >> 4;
    int col = (idx & 15) << 2;
    float4 q = *(const float4*)(Qb + row * DH + col);
    float4 k = *(const float4*)(Kb + row * DH + col);
    uint32_t* qd_ = Qs + row * PT + col;
    qd_[0] = cvt_tf32(q.x); qd_[1] = cvt_tf32(q.y);
    qd_[2] = cvt_tf32(q.z); qd_[3] = cvt_tf32(q.w);
    uint32_t* kd_ = Ks + row * PT + col;
    kd_[0] = cvt_tf32(k.x); kd_[1] = cvt_tf32(k.y);
    kd_[2] = cvt_tf32(k.z); kd_[3] = cvt_tf32(k.w);
  }
  __syncthreads();

  // Accumulators: 2 m-tiles x 8 n-tiles x 4 regs (warp tile 32x64).
  float c[2][8][4];
  #pragma unroll
  for (int mt = 0; mt < 2; mt++)
    #pragma unroll
    for (int nt = 0; nt < 8; nt++)
      #pragma unroll
      for (int j = 0; j < 4; j++) c[mt][nt][j] = 0.0f;

  #pragma unroll
  for (int ks = 0; ks < 8; ks++){
    const int k0 = ks << 3;
    uint32_t a[2][4];
    #pragma unroll
    for (int mt = 0; mt < 2; mt++){
      int rbase = (wm << 5) + (mt << 4) + g;
      a[mt][0] = Qs[ rbase      * PT + k0 + qd];
      a[mt][1] = Qs[(rbase + 8) * PT + k0 + qd];
      a[mt][2] = Qs[ rbase      * PT + k0 + qd + 4];
      a[mt][3] = Qs[(rbase + 8) * PT + k0 + qd + 4];
    }
    #pragma unroll
    for (int nt = 0; nt < 8; nt++){
      int nbase = (wn << 6) + (nt << 3) + g;
      uint32_t b0 = Ks[nbase * PT + k0 + qd];
      uint32_t b1 = Ks[nbase * PT + k0 + qd + 4];
      mma_tf32(c[0][nt], a[0], b0, b1);
      mma_tf32(c[1][nt], a[1], b0, b1);
    }
  }

  // Epilogue: per-row approx max -> atomicMax -> flags -> exact recompute.
  float ths[2][2];
  unsigned fl[2] = {0u, 0u};
  #pragma unroll
  for (int mt = 0; mt < 2; mt++){
    #pragma unroll
    for (int rr = 0; rr < 2; rr++){
      const int r = (wm << 5) + (mt << 4) + (rr << 3) + g;
      float lmax = -1e9f;
      #pragma unroll
      for (int nt = 0; nt < 8; nt++){
        int cb = (wn << 6) + (nt << 3) + (qd << 1);
        float v0 = c[mt][nt][rr * 2 + 0];
        float v1 = c[mt][nt][rr * 2 + 1];
        if (smask[cb])     lmax = fmaxf(lmax, v0);
        if (smask[cb + 1]) lmax = fmaxf(lmax, v1);
      }
      lmax = fmaxf(lmax, __shfl_xor_sync(0xffffffffu, lmax, 1));
      lmax = fmaxf(lmax, __shfl_xor_sync(0xffffffffu, lmax, 2));
      const int grow = bh * S_LEN + tm + r;
      float newmax = 0.0f;
      if (qd == 0){
        int old = atomicMax(&g_rowmax[grow], __float_as_int(lmax));
        newmax = fmaxf(lmax, __int_as_float(old));
      }
      newmax = __shfl_sync(0xffffffffu, newmax, lane & ~3);
      ths[mt][rr] = newmax - 0.19f;   // 0.03 slack + 2 x 0.065 tf32 margin
    }
  }
  #pragma unroll
  for (int mt = 0; mt < 2; mt++)
    #pragma unroll
    for (int nt = 0; nt < 8; nt++)
      #pragma unroll
      for (int rr = 0; rr < 2; rr++)
        #pragma unroll
        for (int jj = 0; jj < 2; jj++){
          int cb = (wn << 6) + (nt << 3) + (qd << 1) + jj;
          unsigned pred = (smask[cb] && c[mt][nt][rr * 2 + jj] >= ths[mt][rr]) ? 1u : 0u;
          int bit = (mt << 5) + (nt << 2) + (rr << 1) + jj;
          fl[bit >> 5] |= pred << (bit & 31);
        }

  #pragma unroll
  for (int wdi = 0; wdi < 2; wdi++){
    unsigned bits = fl[wdi];
    while (bits){
      int p = __ffs(bits) - 1; bits &= bits - 1;
      int code = (wdi << 5) + p;
      int mt = code >> 5, rem = code & 31;
      int nt = rem >> 2, rr = (rem >> 1) & 1, jj = rem & 1;
      int r  = (wm << 5) + (mt << 4) + (rr << 3) + g;
      int cc = (wn << 6) + (nt << 3) + (qd << 1) + jj;
      // exact fp32 recompute from global (L1-hot)
      const float* qr = Qb + r * DH;
      const float* kr = Kb + cc * DH;
      float acc = 0.0f;
      #pragma unroll 16
      for (int d = 0; d < DH; d++) acc += qr[d] * kr[d];
      float ap = c[mt][nt][rr * 2 + jj];
      // sanity gate: if the MMA path is broken, insert nothing -> exact fallback
      if (fabsf(acc - ap) <= 0.5f){
        int grow = bh * S_LEN + tm + r;
        int pos = atomicAdd(&g_rowcnt[grow], 1);
        if (pos < CAP){
          g_cidx[(size_t)grow * CAP + pos] = tn + cc;
          g_cval[(size_t)grow * CAP + pos] = acc;
        }
      }
    }
  }
}

// ============ Kernel 2: warp-per-row candidate softmax + PV ============
__global__ __launch_bounds__(256)
void scatter_pv(const float* __restrict__ Q, const float* __restrict__ K,
                const float* __restrict__ V, const int* __restrict__ mask,
                float* __restrict__ P, float* __restrict__ Out)
{
  const int wid  = threadIdx.x >> 5;
  const int lane = threadIdx.x & 31;
  const int row  = (blockIdx.x << 3) + wid;
  const int bh   = row >> 11;
  const float* Vb = V + (size_t)bh * S_LEN * DH;
  float* Pr = P + (size_t)row * S_LEN;

  const size_t cbase = (size_t)row * CAP;
  const int cnt = g_rowcnt[row];
  // reset metadata for next graph replay (warp owns this row)
  if (lane == 0){ g_rowcnt[row] = 0; g_rowmax[row] = 0; }

  bool fast = false;
  float vals[CAP/32]; int idxs[CAP/32];
  int nchunk = 0;
  float vmax = -3.0e38f;
  if (cnt > 0 && cnt <= CAP){
    nchunk = (cnt + 31) >> 5;
    for (int c = 0; c < nchunk; c++){
      int i = (c << 5) + lane;
      float v = -3.0e38f; int id = 0;
      if (i < cnt){ id = g_cidx[cbase + i]; v = g_cval[cbase + i]; }
      vals[c] = v; idxs[c] = id;
      vmax = fmaxf(vmax, v);
    }
    #pragma unroll
    for (int off = 16; off; off >>= 1) vmax = fmaxf(vmax, __shfl_xor_sync(0xffffffffu, vmax, off));
    fast = (vmax >= 14.0f);
  }

  if (fast){
    const float smaxv = expf(vmax) * 0.125f;
    float lsum = 0.0f;
    for (int c = 0; c < nchunk; c++){
      int i = (c << 5) + lane;
      float e = 0.0f;
      if (i < cnt){ e = expf(expf(vals[c]) * 0.125f - smaxv); lsum += e; }
      vals[c] = e;
    }
    #pragma unroll
    for (int off = 16; off; off >>= 1) lsum += __shfl_xor_sync(0xffffffffu, lsum, off);
    const float inv = 1.0f / lsum;

    float o0 = 0.0f, o1 = 0.0f;
    for (int c = 0; c < nchunk; c++){
      int i = (c << 5) + lane;
      float p = vals[c] * inv;
      if (i < cnt) Pr[idxs[c]] = p;
      unsigned mnz = __ballot_sync(0xffffffffu, (i < cnt) && (p != 0.0f));
      while (mnz){
        int src = __ffs(mnz) - 1; mnz &= mnz - 1;
        float pv = __shfl_sync(0xffffffffu, p, src);
        int  key = __shfl_sync(0xffffffffu, idxs[c], src);
        const float* vr = Vb + (size_t)key * DH;
        o0 += pv * vr[lane];
        o1 += pv * vr[lane + 32];
      }
    }
    Out[(size_t)row * DH + lane]      = o0;
    Out[(size_t)row * DH + lane + 32] = o1;
  } else {
    // ---- exact fallback (reference semantics), warp-only, 3-pass ----
    const float* Qr = Q + (size_t)row * DH;
    const float* Kb = K + (size_t)bh * S_LEN * DH;
    const int*   mrow = mask + (bh >> 3) * S_LEN;

    float mx = -3.0e38f;
    for (int key = lane; key < S_LEN; key += 32){
      float acc = 0.0f;
      #pragma unroll 16
      for (int d = 0; d < DH; d++) acc += Qr[d] * Kb[(size_t)key * DH + d];
      float qkv = mrow[key] ? acc : -1e9f;
      mx = fmaxf(mx, qkv);
    }
    #pragma unroll
    for (int off = 16; off; off >>= 1) mx = fmaxf(mx, __shfl_xor_sync(0xffffffffu, mx, off));
    const float qmax = mx;
    const float smax_s = (qmax <= -1e8f) ? -1e9f : expf(qmax) * 0.125f;

    float lsum = 0.0f;
    for (int key = lane; key < S_LEN; key += 32){
      float acc = 0.0f;
      #pragma unroll 16
      for (int d = 0; d < DH; d++) acc += Qr[d] * Kb[(size_t)key * DH + d];
      float qkv = mrow[key] ? acc : -1e9f;
      float s = (qkv <= -1e8f) ? -1e9f : expf(qkv) * 0.125f;
      lsum += expf(s - smax_s);
    }
    #pragma unroll
    for (int off = 16; off; off >>= 1) lsum += __shfl_xor_sync(0xffffffffu, lsum, off);
    const float inv = 1.0f / lsum;

    float o0 = 0.0f, o1 = 0.0f;
    for (int key0 = 0; key0 < S_LEN; key0 += 32){
      int key = key0 + lane;
      float acc = 0.0f;
      #pragma unroll 16
      for (int d = 0; d < DH; d++) acc += Qr[d] * Kb[(size_t)key * DH + d];
      float qkv = mrow[key] ? acc : -1e9f;
      float s = (qkv <= -1e8f) ? -1e9f : expf(qkv) * 0.125f;
      float p = expf(s - smax_s) * inv;
      Pr[key] = p;
      #pragma unroll
      for (int src = 0; src < 32; src++){
        float pv = __shfl_sync(0xffffffffu, p, src);
        if (pv != 0.0f){
          const float* vr = Vb + (size_t)(key0 + src) * DH;
          o0 += pv * vr[lane];
          o1 += pv * vr[lane + 32];
        }
      }
    }
    Out[(size_t)row * DH + lane]      = o0;
    Out[(size_t)row * DH + lane + 32] = o1;
  }
}

extern "C" void kernel_launch(void* const* d_in, const int* in_sizes, int n_in,
                              void* d_out, int out_size)
{
  const float* Q    = (const float*)d_in[0];
  const float* K    = (const float*)d_in[1];
  const float* V    = (const float*)d_in[2];
  const int*   mask = (const int*)d_in[3];

  float* Out = (float*)d_out;                        // (B,H,S,D)
  float* P   = Out + (size_t)NB * NH * S_LEN * DH;   // (B,H,S,S)

  const int smem = 512 + 2 * 128 * PT * 4;           // 70144 B
  cudaFuncSetAttribute(qk_mma, cudaFuncAttributeMaxDynamicSharedMemorySize, smem);
  dim3 g1(S_LEN / 128, S_LEN / 128, NB * NH);        // 16 x 16 x 16
  qk_mma<<<g1, 256, smem>>>(Q, K, mask, P);

  scatter_pv<<<NROWS / 8, 256>>>(Q, K, V, mask, P, Out);
}